// round 17
// baseline (speedup 1.0000x reference)
#include <cuda_runtime.h>
#include <cuda.h>
#include <cuda_fp16.h>
#include <cstdint>

// out[bn] = A @ x[bn]^T @ B.  R16: 3 CTAs/SM (launch_bounds(256,3), NST=2,
// SMEM 66.6KB) to fix the latency-bound plateau (no pipe >61% at 2 CTAs).
// A-fragments re-loaded per k-step (transient regs) to fit the 84-reg budget.
// G1: T[a=64, p=224pad] = sum_c A[a,c] x[p,c]  (K=768, 24 chunks of 32, fp16 mma)
// G2: out[a,h] = sum_p T[a,p] B[p,h]           (K=224, fp16 mma)
#define P_DIM 196
#define C_DIM 768
#define NCH 24
#define PP 224
#define XST_B (PP * 128)              // 28672 X region per stage (f32, SW128)
#define AST_B (64 * 64)               // 4096  A region per stage (f16, 64B rows)
#define STG_B (XST_B + AST_B)         // 32768
#define NST 2
#define STAGES_B (NST * STG_B)        // 65536
#define TPITCH 232                    // halves per T/Bs row
#define OFF_TS 0
#define OFF_BS (64 * TPITCH * 2)      // 29696 (T+Bs end 59392 <= 65536, alias both stages)
#define MB_OFF STAGES_B               // full[0],full[1] at +0,+8
#define SMEM_ALLOC (STAGES_B + 64 + 1024)   // 66624 -> 3 CTAs/SM
#define TX_BYTES (P_DIM * 128 + AST_B)   // 29184 per stage

#define DEVINL __device__ __forceinline__

__device__ __half g_Ah[64 * C_DIM];   // A pre-rounded to f16 (RN)

DEVINL uint32_t smem_u32(const void* p) {
    uint32_t a;
    asm("{ .reg .u64 t; cvta.to.shared.u64 t, %1; cvt.u32.u64 %0, t; }" : "=r"(a) : "l"(p));
    return a;
}
DEVINL uint32_t f2h2(float lo, float hi) {
    __half2 h = __floats2half2_rn(lo, hi);
    return *reinterpret_cast<uint32_t*>(&h);
}
DEVINL float4 lds128(uint32_t addr) {
    float4 v;
    asm volatile("ld.shared.v4.f32 {%0,%1,%2,%3}, [%4];"
                 : "=f"(v.x), "=f"(v.y), "=f"(v.z), "=f"(v.w) : "r"(addr));
    return v;
}
DEVINL void lds128u(uint32_t* r, uint32_t addr) {
    asm volatile("ld.shared.v4.b32 {%0,%1,%2,%3}, [%4];"
                 : "=r"(r[0]), "=r"(r[1]), "=r"(r[2]), "=r"(r[3]) : "r"(addr));
}
DEVINL void ldsm4(uint32_t* r, uint32_t addr) {
    asm volatile("ldmatrix.sync.aligned.m8n8.x4.shared.b16 {%0,%1,%2,%3}, [%4];"
                 : "=r"(r[0]), "=r"(r[1]), "=r"(r[2]), "=r"(r[3]) : "r"(addr));
}
DEVINL void mma16816(float* d, uint32_t a0, uint32_t a1, uint32_t a2, uint32_t a3,
                     uint32_t b0, uint32_t b1) {
    asm volatile("mma.sync.aligned.m16n8k16.row.col.f32.f16.f16.f32 "
                 "{%0,%1,%2,%3}, {%4,%5,%6,%7}, {%8,%9}, {%0,%1,%2,%3};"
                 : "+f"(d[0]), "+f"(d[1]), "+f"(d[2]), "+f"(d[3])
                 : "r"(a0), "r"(a1), "r"(a2), "r"(a3), "r"(b0), "r"(b1));
}

#define MBAR_INIT(a, c) \
    asm volatile("mbarrier.init.shared.b64 [%0], %1;" :: "r"((uint32_t)(a)), "r"((uint32_t)(c)) : "memory")
#define MBAR_EXPECT_TX(a, b) \
    asm volatile("mbarrier.arrive.expect_tx.shared.b64 _, [%0], %1;" :: "r"((uint32_t)(a)), "r"((uint32_t)(b)) : "memory")
#define MBAR_WAIT(a, p) do {                                                              \
    asm volatile("{ .reg .pred P; WL%=:\n\t"                                              \
        "mbarrier.try_wait.parity.acquire.cta.shared::cta.b64 P, [%0], %1, 0x989680;\n\t" \
        "@P bra.uni WD%=;\n\t bra.uni WL%=;\n\t WD%=: }"                                  \
        :: "r"((uint32_t)(a)), "r"((uint32_t)(p)) : "memory");                            \
} while (0)
#define TMA_2D(dst, map, cx, cy, mb) \
    asm volatile("cp.async.bulk.tensor.2d.shared::cta.global.tile.mbarrier::complete_tx::bytes " \
        "[%0], [%1, {%2, %3}], [%4];" \
        :: "r"((uint32_t)(dst)), "l"(map), "r"((int)(cx)), "r"((int)(cy)), "r"((uint32_t)(mb)) : "memory")
#define TMA_3D(dst, map, cx, cy, cz, mb) \
    asm volatile("cp.async.bulk.tensor.3d.shared::cta.global.tile.mbarrier::complete_tx::bytes " \
        "[%0], [%1, {%2, %3, %4}], [%5];" \
        :: "r"((uint32_t)(dst)), "l"(map), "r"((int)(cx)), "r"((int)(cy)), "r"((int)(cz)), "r"((uint32_t)(mb)) : "memory")

__global__ void cvt_A_kernel(const float* __restrict__ A) {
    int i = blockIdx.x * 256 + threadIdx.x;
    if (i < 64 * C_DIM) g_Ah[i] = __float2half_rn(A[i]);
}

__global__ void __launch_bounds__(256, 3) sepnet_tma_kernel(
    const float* __restrict__ Bmat, float* __restrict__ out,
    const __grid_constant__ CUtensorMap tmX,
    const __grid_constant__ CUtensorMap tmA)
{
    extern __shared__ char smem_raw[];
    const uint32_t sb = (smem_u32(smem_raw) + 1023) & ~1023u;
    const int tid = threadIdx.x;
    const int wid = tid >> 5;
    const int lane = tid & 31;
    const int bn = blockIdx.x;

    if (tid == 0) {
        MBAR_INIT(sb + MB_OFF + 0, 1);
        MBAR_INIT(sb + MB_OFF + 8, 1);
    }
    // zero X pad rows (196..223) in both stages
    for (int i = tid; i < NST * 896; i += 256) {
        int s = i / 896, w = i % 896;
        asm volatile("st.shared.b32 [%0], %1;"
            :: "r"(sb + s * STG_B + P_DIM * 128 + w * 4), "r"(0u) : "memory");
    }
    __syncthreads();
    if (tid == 0) {
#pragma unroll
        for (int pre = 0; pre < 2; pre++) {
            uint32_t mb = sb + MB_OFF + 8 * pre;
            MBAR_EXPECT_TX(mb, TX_BYTES);
            TMA_3D(sb + pre * STG_B, &tmX, pre * 32, 0, bn, mb);
            TMA_2D(sb + pre * STG_B + XST_B, &tmA, pre * 32, 0, mb);
        }
    }

    // ---- G1: fp16 mma, warp = (agrp: 32 a-rows) x (pgrp: 56 p-cols) ----
    float acc[2][7][4];
#pragma unroll
    for (int m = 0; m < 2; m++)
#pragma unroll
        for (int t = 0; t < 7; t++)
            acc[m][t][0] = acc[m][t][1] = acc[m][t][2] = acc[m][t][3] = 0.0f;

    const int abase = (wid & 1) * 32;
    const int pbase = (wid >> 1) * 56;
    const int rr = lane >> 2;
    const int q = lane & 3;

    for (int ch = 0; ch < NCH; ch++) {
        const int s = ch & 1;
        MBAR_WAIT(sb + MB_OFF + 8 * s, (uint32_t)((ch >> 1) & 1));

        const uint32_t Xb = sb + s * STG_B;
        const uint32_t Ab = Xb + XST_B;
#pragma unroll
        for (int ks = 0; ks < 2; ks++) {
            const uint32_t coff = (uint32_t)((2 * q + ks) ^ rr) << 4;
            // A fragments re-loaded per ks (transient regs; unused halves die)
            uint32_t t0[4], t1[4], t2[4], t3[4];
            lds128u(t0, Ab + (uint32_t)(abase + rr) * 64 + (uint32_t)q * 16);
            lds128u(t1, Ab + (uint32_t)(abase + rr + 8) * 64 + (uint32_t)q * 16);
            lds128u(t2, Ab + (uint32_t)(abase + 16 + rr) * 64 + (uint32_t)q * 16);
            lds128u(t3, Ab + (uint32_t)(abase + 16 + rr + 8) * 64 + (uint32_t)q * 16);
#pragma unroll
            for (int t = 0; t < 7; t++) {
                float4 v = lds128(Xb + (uint32_t)(pbase + t * 8 + rr) * 128 + coff);
                uint32_t b0 = f2h2(v.x, v.y);
                uint32_t b1 = f2h2(v.z, v.w);
                mma16816(acc[0][t], t0[2 * ks], t1[2 * ks], t0[2 * ks + 1], t1[2 * ks + 1], b0, b1);
                mma16816(acc[1][t], t2[2 * ks], t3[2 * ks], t2[2 * ks + 1], t3[2 * ks + 1], b0, b1);
            }
        }
        __syncthreads();   // all warps done with stage s -> safe to overwrite
        if (tid == 0 && ch + 2 < NCH) {
            uint32_t mb = sb + MB_OFF + 8 * s;
            MBAR_EXPECT_TX(mb, TX_BYTES);
            TMA_3D(sb + s * STG_B, &tmX, (ch + 2) * 32, 0, bn, mb);
            TMA_2D(sb + s * STG_B + XST_B, &tmA, (ch + 2) * 32, 0, mb);
        }
    }

    // ---- T (f16) into alias region (both stages dead after last sync) ----
    {
        const int cb = pbase + (lane & 3) * 2;
#pragma unroll
        for (int m = 0; m < 2; m++) {
            const int r0 = abase + m * 16 + (lane >> 2);
#pragma unroll
            for (int t = 0; t < 7; t++) {
                int c = cb + t * 8;
                asm volatile("st.shared.b32 [%0], %1;"
                    :: "r"(sb + OFF_TS + (r0 * TPITCH + c) * 2), "r"(f2h2(acc[m][t][0], acc[m][t][1])) : "memory");
                asm volatile("st.shared.b32 [%0], %1;"
                    :: "r"(sb + OFF_TS + ((r0 + 8) * TPITCH + c) * 2), "r"(f2h2(acc[m][t][2], acc[m][t][3])) : "memory");
            }
        }
    }
    // Bs[h][p] f16, pads zero
    for (int i = tid; i < 64 * PP; i += 256) {
        int p = i >> 6, h = i & 63;
        float v = (p < P_DIM) ? Bmat[p * 64 + h] : 0.0f;
        unsigned short hb = __half_as_ushort(__float2half_rn(v));
        asm volatile("st.shared.b16 [%0], %1;"
            :: "r"(sb + OFF_BS + (h * TPITCH + p) * 2), "h"(hb) : "memory");
    }
    __syncthreads();

    // ---- G2: out[a,h] = sum_p T[a,p] Bs[h,p], K = 224, fp16 ----
    float o[4][4];
#pragma unroll
    for (int i = 0; i < 4; i++)
        o[i][0] = o[i][1] = o[i][2] = o[i][3] = 0.0f;
    const uint32_t tsb = sb + OFF_TS;
    const uint32_t bsb = sb + OFF_BS;
    const int a2row = (wid >> 1) * 16 + (lane & 15);
    const int a2co = (lane & 16) ? 8 : 0;
    const int hhalf = (wid & 1) * 32;
    const int browofs = (lane & 7) + ((lane & 16) >> 1);
    const int bcolofs = ((lane >> 3) & 1) * 8;
#pragma unroll
    for (int ks = 0; ks < 14; ks++) {
        const int k0 = ks * 16;
        uint32_t a[4];
        ldsm4(a, tsb + (a2row * TPITCH + k0 + a2co) * 2);
#pragma unroll
        for (int g = 0; g < 2; g++) {
            uint32_t b[4];
            ldsm4(b, bsb + ((hhalf + g * 16 + browofs) * TPITCH + k0 + bcolofs) * 2);
            mma16816(o[2 * g], a[0], a[1], a[2], a[3], b[0], b[1]);
            mma16816(o[2 * g + 1], a[0], a[1], a[2], a[3], b[2], b[3]);
        }
    }
    {
        float* ob = out + (size_t)bn * 4096;
        const int r0 = (wid >> 1) * 16 + lane / 4;
        const int cb = hhalf + (lane & 3) * 2;
#pragma unroll
        for (int nt = 0; nt < 4; nt++) {
            int c = cb + nt * 8;
            *reinterpret_cast<float2*>(ob + r0 * 64 + c) = make_float2(o[nt][0], o[nt][1]);
            *reinterpret_cast<float2*>(ob + (r0 + 8) * 64 + c) = make_float2(o[nt][2], o[nt][3]);
        }
    }
}

extern "C" void kernel_launch(void* const* d_in, const int* in_sizes, int n_in,
                              void* d_out, int out_size) {
    int ix = 0, ia = 1, ib = 2;
    for (int i = 0; i < n_in; i++) {
        if (in_sizes[i] == 237244416) ix = i;
        else if (in_sizes[i] == 49152) ia = i;
        else if (in_sizes[i] == 12544) ib = i;
    }
    void* xp = d_in[ix];
    const float* A = (const float*)d_in[ia];
    const float* B = (const float*)d_in[ib];
    float* out = (float*)d_out;

    void* ah_ptr = nullptr;
    cudaGetSymbolAddress(&ah_ptr, g_Ah);

    typedef CUresult (CUDAAPI * EncFn)(
        CUtensorMap*, CUtensorMapDataType, cuuint32_t, void*,
        const cuuint64_t*, const cuuint64_t*, const cuuint32_t*, const cuuint32_t*,
        CUtensorMapInterleave, CUtensorMapSwizzle, CUtensorMapL2promotion, CUtensorMapFloatOOBfill);
    void* fnp = nullptr;
    cudaDriverEntryPointQueryResult qr;
    cudaGetDriverEntryPointByVersion("cuTensorMapEncodeTiled", &fnp, 12000,
                                     cudaEnableDefault, &qr);
    EncFn enc = (EncFn)fnp;

    CUtensorMap tmX, tmA;
    {
        cuuint64_t dims[3] = { (cuuint64_t)C_DIM, (cuuint64_t)P_DIM, 1576 };
        cuuint64_t strides[2] = { (cuuint64_t)C_DIM * 4, (cuuint64_t)P_DIM * C_DIM * 4 };
        cuuint32_t box[3] = { 32, (cuuint32_t)P_DIM, 1 };
        cuuint32_t es[3] = { 1, 1, 1 };
        enc(&tmX, CU_TENSOR_MAP_DATA_TYPE_FLOAT32, 3, xp, dims, strides, box, es,
            CU_TENSOR_MAP_INTERLEAVE_NONE, CU_TENSOR_MAP_SWIZZLE_128B,
            CU_TENSOR_MAP_L2_PROMOTION_L2_128B, CU_TENSOR_MAP_FLOAT_OOB_FILL_NONE);
    }
    {
        cuuint64_t dims[2] = { (cuuint64_t)C_DIM, 64 };
        cuuint64_t strides[1] = { (cuuint64_t)C_DIM * 2 };
        cuuint32_t box[2] = { 32, 64 };
        cuuint32_t es[2] = { 1, 1 };
        enc(&tmA, CU_TENSOR_MAP_DATA_TYPE_FLOAT16, 2, ah_ptr, dims, strides, box, es,
            CU_TENSOR_MAP_INTERLEAVE_NONE, CU_TENSOR_MAP_SWIZZLE_NONE,
            CU_TENSOR_MAP_L2_PROMOTION_L2_128B, CU_TENSOR_MAP_FLOAT_OOB_FILL_NONE);
    }

    cvt_A_kernel<<<(64 * C_DIM + 255) / 256, 256>>>(A);
    cudaFuncSetAttribute(sepnet_tma_kernel,
                         cudaFuncAttributeMaxDynamicSharedMemorySize, SMEM_ALLOC);
    sepnet_tma_kernel<<<1576, 256, SMEM_ALLOC>>>(B, out, tmX, tmA);
}